// round 12
// baseline (speedup 1.0000x reference)
#include <cuda_runtime.h>

#define HIDDEN    128
#define MAX_NODES 100000
#define NBLK      592          // 4 blocks/SM x 148 SMs -> all co-resident (no deadlock)
#define NFLAGS    148

// Scratch (device globals; allocation is forbidden).
// Gap form: softmax over 2 classes depends only on l0-l1, so per node keep
//   gs[n] = n·dA,  gd[n] = n·dB,  dA/dB = W1 halves @ (w2_0 - w2_1).
__device__ float  g_GS[MAX_NODES];
__device__ float  g_GD[MAX_NODES];
__device__ float4 g_dAv[32], g_dBv[32];   // dA, dB as 32 x float4
__device__ float  g_gapb;                 // b1·(w2_0-w2_1) + b2_0 - b2_1
__device__ int    g_is64;
__device__ int    g_done;                 // fused-kernel node-phase counter
__device__ int    g_flags[NFLAGS * 32];   // release flag mirrored per 128B line

// ---------------------------------------------------------------------------
// Kernel A: collapse both layers into the gap direction (block-per-row) and
// reset the fused kernel's sync state for this replay (stream-ordered: this
// kernel completes before the fused kernel launches).
//   dA[i] = sum_k W1[i][k]     * (W2[k][0]-W2[k][1])   i in [0,128)
//   dB[i] = sum_k W1[128+i][k] * (W2[k][0]-W2[k][1])
//   block 256: gap bias;  block 257: dtype probe + state reset.
// ---------------------------------------------------------------------------
__global__ void __launch_bounds__(256) combine_kernel(
        const float* __restrict__ W1, const float* __restrict__ b1,
        const float* __restrict__ W2, const float* __restrict__ b2,
        const long long* __restrict__ edges_as_i64, int n_edges)
{
    __shared__ float red[8];
    int b    = blockIdx.x;
    int tid  = threadIdx.x;
    int warp = tid >> 5;
    int lane = tid & 31;

    if (b < 257) {
        float w0 = W2[2 * tid]         - W2[2 * tid + 1];
        float w1 = W2[2 * (tid + 256)] - W2[2 * (tid + 256) + 1];
        const float* row = (b < 256) ? (W1 + (size_t)b * (4 * HIDDEN)) : b1;
        float acc = row[tid] * w0 + row[tid + 256] * w1;

        #pragma unroll
        for (int o = 16; o; o >>= 1) acc += __shfl_xor_sync(0xffffffffu, acc, o);
        if (lane == 0) red[warp] = acc;
        __syncthreads();
        if (warp == 0) {
            float v = (lane < 8) ? red[lane] : 0.f;
            #pragma unroll
            for (int o = 4; o; o >>= 1) v += __shfl_xor_sync(0xffffffffu, v, o);
            if (lane == 0) {
                if (b < HIDDEN)   ((float*)g_dAv)[b] = v;
                else if (b < 256) ((float*)g_dBv)[b - HIDDEN] = v;
                else              g_gapb = v + b2[0] - b2[1];
            }
        }
    } else {
        if (warp == 0) {
            // Dtype probe: an int32 buffer misread as int64 pairs fails the
            // [0, MAX_NODES) range check almost surely over 64 samples.
            int ok = 1;
            #pragma unroll
            for (int r = 0; r < 2; ++r) {
                int t = r * 32 + lane;
                if (t < n_edges) {
                    long long v = edges_as_i64[t];
                    if (v < 0 || v >= (long long)MAX_NODES) ok = 0;
                }
            }
            ok = __all_sync(0xffffffffu, ok);
            if (lane == 0) g_is64 = ok;
        } else if (tid >= 32 && tid < 32 + NFLAGS) {
            g_flags[(tid - 32) * 32] = 0;          // reset mirrored flags
        } else if (tid == 224) {
            g_done = 0;                            // reset counter
        }
    }
}

// ---------------------------------------------------------------------------
// Fused node+edge kernel (persistent, 592 co-resident blocks).
//  Phase 1: per-node gap projections, chunks of 64 nodes per block iteration
//           (8 nodes/warp, row loads front-batched).
//  Sync:    atomic completion counter; last block mirrors the release flag
//           to 148 cache lines; tid0-only poll + __syncthreads.
//  Phase 2: 2 edges/thread strided over pairs; 4B gathers from the two
//           L2-resident 400 KB tables; sigmoid of the logit gap.
// ---------------------------------------------------------------------------
__global__ void __launch_bounds__(256, 4) fused_ne_kernel(
        const float* __restrict__ feat, const void* __restrict__ edges,
        float2* __restrict__ out, int n_nodes, int n_edges)
{
    int tid  = threadIdx.x;
    int warp = tid >> 5;
    int lane = tid & 31;

    float4 wa = g_dAv[lane];      // ready: combine kernel ran before us
    float4 wb = g_dBv[lane];

    // ---- Phase 1: node projections ----
    int nchunks = (n_nodes + 63) >> 6;
    for (int c = blockIdx.x; c < nchunks; c += NBLK) {
        int node0 = c * 64 + warp * 8;
        float4 x[8];
        #pragma unroll
        for (int r = 0; r < 8; ++r) {
            int node = node0 + r;
            if (node < n_nodes)
                x[r] = reinterpret_cast<const float4*>(feat + (size_t)node * HIDDEN)[lane];
        }
        #pragma unroll
        for (int r = 0; r < 8; ++r) {
            int node = node0 + r;
            if (node >= n_nodes) break;
            float gs = x[r].x * wa.x + x[r].y * wa.y + x[r].z * wa.z + x[r].w * wa.w;
            float gd = x[r].x * wb.x + x[r].y * wb.y + x[r].z * wb.z + x[r].w * wb.w;
            #pragma unroll
            for (int o = 16; o; o >>= 1) {
                gs += __shfl_xor_sync(0xffffffffu, gs, o);
                gd += __shfl_xor_sync(0xffffffffu, gd, o);
            }
            if (lane == 0) {
                g_GS[node] = gs;
                g_GD[node] = gd;
            }
        }
    }

    // ---- Signal node-phase completion ----
    __syncthreads();
    if (tid == 0) {
        __threadfence();                                  // publish GS/GD
        if (atomicAdd(&g_done, 1) == NBLK - 1) {
            #pragma unroll 4
            for (int f = 0; f < NFLAGS; ++f)
                *(volatile int*)&g_flags[f * 32] = 1;     // mirrored release
        }
    }

    // ---- Wait (tid0-only, private flag line per block) ----
    if (tid == 0) {
        volatile int* f = &g_flags[(blockIdx.x % NFLAGS) * 32];
        while (*f == 0) __nanosleep(64);
        __threadfence();                                  // acquire
    }
    __syncthreads();

    // ---- Phase 2: edges ----
    float gapb = g_gapb;
    int   is64 = g_is64;
    int npairs = (n_edges + 1) >> 1;
    bool  even = (n_edges & 1) == 0;

    for (int p = blockIdx.x * 256 + tid; p < npairs; p += NBLK * 256) {
        int base = p * 2;
        if (even) {
            int s0, s1, d0, d1;
            if (is64) {
                const longlong2* E = (const longlong2*)edges;
                longlong2 s = E[base >> 1];
                longlong2 d = E[(n_edges + base) >> 1];
                s0 = (int)s.x; s1 = (int)s.y; d0 = (int)d.x; d1 = (int)d.y;
            } else {
                const int2* E = (const int2*)edges;
                int2 s = E[base >> 1];
                int2 d = E[(n_edges + base) >> 1];
                s0 = s.x; s1 = s.y; d0 = d.x; d1 = d.y;
            }
            float gs0 = __ldg(&g_GS[s0]);
            float gs1 = __ldg(&g_GS[s1]);
            float gd0 = __ldg(&g_GD[d0]);
            float gd1 = __ldg(&g_GD[d1]);

            float p0 = 1.0f / (1.0f + __expf(gs0 + gd0 + gapb));
            float p1 = 1.0f / (1.0f + __expf(gs1 + gd1 + gapb));
            *(float4*)(out + base) = make_float4(1.0f - p0, p0, 1.0f - p1, p1);
        } else {
            // odd n_edges: fully scalar (alignment not guaranteed)
            int lim = base + 2 < n_edges ? base + 2 : n_edges;
            for (int e = base; e < lim; ++e) {
                int si, di;
                if (is64) {
                    const long long* E = (const long long*)edges;
                    si = (int)E[e]; di = (int)E[e + n_edges];
                } else {
                    const int* E = (const int*)edges;
                    si = E[e]; di = E[e + n_edges];
                }
                float pr = 1.0f / (1.0f + __expf(__ldg(&g_GS[si]) + __ldg(&g_GD[di]) + gapb));
                out[e] = make_float2(1.0f - pr, pr);
            }
        }
    }
}

// ---------------------------------------------------------------------------
// Launch. metadata order:
//   0: node_features_after_gcn (float32, N_NODES*128)
//   1: edges                   (int64 or int32, 2*N_EDGES)
//   2: W1 (256*512)  3: b1 (512)  4: W2 (512*2)  5: b2 (2)
// ---------------------------------------------------------------------------
extern "C" void kernel_launch(void* const* d_in, const int* in_sizes, int n_in,
                              void* d_out, int out_size)
{
    const float* feat  = (const float*)d_in[0];
    const void*  edges = d_in[1];
    const float* W1    = (const float*)d_in[2];
    const float* b1    = (const float*)d_in[3];
    const float* W2    = (const float*)d_in[4];
    const float* b2    = (const float*)d_in[5];

    int n_nodes = in_sizes[0] / HIDDEN;
    if (n_nodes > MAX_NODES) n_nodes = MAX_NODES;
    int n_edges = in_sizes[1] / 2;

    // A: block-per-row combine + sync-state reset. 258 blocks.
    combine_kernel<<<258, 256>>>(W1, b1, W2, b2, (const long long*)edges, n_edges);

    // B: persistent fused node+edge.
    fused_ne_kernel<<<NBLK, 256>>>(feat, edges, (float2*)d_out, n_nodes, n_edges);
}